// round 6
// baseline (speedup 1.0000x reference)
#include <cuda_runtime.h>
#include <math_constants.h>

// Problem constants
#define NB 32
#define NP 576
#define ND 768
#define KP1 17
#define KF 16
#define NC 200
#define NDV 192       // ulonglong2 (16B) per 768-float row
#define PAD_K 20      // g_a row pad: 80B, 16B-aligned

// Output layout: concatenation of (A, v_norm, logits_parts, logits_agg)
#define SZ_A (NB*KP1*NP)            // 313344
#define OFF_VN (SZ_A)
#define SZ_VN (NB*KF*ND)            // 393216
#define OFF_PARTS (OFF_VN + SZ_VN)
#define SZ_PARTS (NB*KF*NC)         // 102400
#define OFF_AGG (OFF_PARTS + SZ_PARTS)

typedef unsigned long long u64;

// v accumulator (pre-LN). Zeroed at module load; k2a re-zeroes after reading,
// so the "g_v == 0 on k1b entry" invariant holds across graph replays.
__device__ float g_v[NB*KF*ND];
// softmax attention scratch, rows padded to PAD_K floats (fully rewritten each launch)
__device__ float g_a[(size_t)NB*NP*PAD_K];

// ---- f32x2 packed-FMA helpers ----------------------------------------------
__device__ __forceinline__ u64 fma2(u64 a, u64 b, u64 c) {
    u64 d; asm("fma.rn.f32x2 %0, %1, %2, %3;" : "=l"(d) : "l"(a), "l"(b), "l"(c));
    return d;
}
__device__ __forceinline__ u64 pack2(float lo, float hi) {
    u64 r; asm("mov.b64 %0, {%1,%2};" : "=l"(r) : "f"(lo), "f"(hi));
    return r;
}
__device__ __forceinline__ float2 unpack2(u64 v) {
    float2 r; asm("mov.b64 {%0,%1}, %2;" : "=f"(r.x), "=f"(r.y) : "l"(v));
    return r;
}

// ---------------------------------------------------------------------------
// k1a: dots + softmax. Proto staged in smem (52 KB); x streamed from DRAM.
// Grid: 576 blocks (b x 18 tiles of 32 patches); 8 warps x 4 patches each.
// Warp owns one patch at a time: acc = 17 u64 = 34 regs only.
// Writes softmax rows (17 vals) to g_a[b][p][0..16].
// ---------------------------------------------------------------------------
__global__ __launch_bounds__(256, 3)
void k1a(const float* __restrict__ x, const float* __restrict__ proto)
{
    extern __shared__ float sm[];
    float* ps     = sm;                    // 17*768 floats (52.2 KB)
    float* a_part = ps + KP1*ND;           // 8 warps * 17 * 4
    float* psq_s  = a_part + 8*KP1*4;      // 17

    const int t = threadIdx.x, warp = t >> 5, lane = t & 31;
    const int b = blockIdx.x / 18, tile = blockIdx.x % 18;

    // stage proto into smem (coalesced float4)
    {
        const float4* pg = (const float4*)proto;
        float4* ps4 = (float4*)ps;
        for (int i = t; i < KP1*ND/4; i += 256) ps4[i] = __ldg(&pg[i]);
    }
    // ||p_k||^2 (from global, overlaps staging)
    for (int k = warp; k < KP1; k += 8) {
        const float4* pk = (const float4*)(proto + (size_t)k*ND);
        float s = 0.f;
        #pragma unroll
        for (int i = 0; i < 6; i++) {
            float4 v = __ldg(&pk[lane + 32*i]);
            s += v.x*v.x + v.y*v.y + v.z*v.z + v.w*v.w;
        }
        #pragma unroll
        for (int o = 16; o; o >>= 1) s += __shfl_xor_sync(0xffffffffu, s, o);
        if (lane == 0) psq_s[k] = s;
    }
    __syncthreads();

    const ulonglong2* ps2 = (const ulonglong2*)ps;
    float* ap = a_part + warp*KP1*4;

    for (int pp = 0; pp < 4; pp++) {
        const int p = tile*32 + warp*4 + pp;
        const ulonglong2* xr = (const ulonglong2*)(x + ((size_t)b*NP + p)*ND);

        u64 acc[KP1];
        #pragma unroll
        for (int k = 0; k < KP1; k++) acc[k] = 0ULL;

        #pragma unroll
        for (int j = 0; j < 6; j++) {
            ulonglong2 xv = __ldg(&xr[j*32 + lane]);   // coalesced 512B
            #pragma unroll
            for (int k = 0; k < KP1; k++) {
                ulonglong2 pv = ps2[k*NDV + j*32 + lane];
                acc[k] = fma2(xv.x, pv.x, acc[k]);
                acc[k] = fma2(xv.y, pv.y, acc[k]);
            }
        }

        // reduce: 3 shfl levels -> 4 partials, lanes 0-3 store
        #pragma unroll
        for (int k = 0; k < KP1; k++) {
            float2 h = unpack2(acc[k]);
            float v = h.x + h.y;
            v += __shfl_xor_sync(0xffffffffu, v, 16);
            v += __shfl_xor_sync(0xffffffffu, v, 8);
            v += __shfl_xor_sync(0xffffffffu, v, 4);
            if (lane < 4) ap[k*4 + lane] = v;
        }
        __syncwarp();

        // lane-parallel softmax: softmax_k(2*xp - psq) == softmax(-dists)
        float s = -CUDART_INF_F;
        if (lane < KP1) {
            float4 t4 = ((const float4*)ap)[lane];
            float dot = (t4.x + t4.y) + (t4.z + t4.w);
            s = fmaf(2.f, dot, -psq_s[lane]);
        }
        float m = s;
        #pragma unroll
        for (int o = 16; o; o >>= 1) m = fmaxf(m, __shfl_xor_sync(0xffffffffu, m, o));
        float e = (lane < KP1) ? __expf(s - m) : 0.f;
        float ssum = e;
        #pragma unroll
        for (int o = 16; o; o >>= 1) ssum += __shfl_xor_sync(0xffffffffu, ssum, o);
        if (lane < KP1)
            g_a[((size_t)b*NP + p)*PAD_K + lane] = e * (1.f / ssum);
        __syncwarp();
    }
}

// ---------------------------------------------------------------------------
// k1b: A transpose-write + v accumulation.
// Grid (16 p-tiles, 32 b), 384 threads; thread owns d-pair (2t, 2t+1).
// vacc: 16 u64 (k-major pairs). x streamed (L2-hot after k1a).
// ---------------------------------------------------------------------------
#define PT 36
__global__ __launch_bounds__(384, 2)
void k1b(const float* __restrict__ x, float* __restrict__ out)
{
    __shared__ float a_sm[PT*PAD_K];       // 2.88 KB
    const int pt = blockIdx.x, b = blockIdx.y, t = threadIdx.x;
    const int p0 = pt*PT;

    // stage a tile (coalesced)
    const float* ga = g_a + ((size_t)b*NP + p0)*PAD_K;
    for (int i = t; i < PT*PAD_K; i += 384) a_sm[i] = ga[i];
    __syncthreads();

    // A output: A[b][k][p0..p0+35], rows contiguous in p
    for (int i = t; i < KP1*PT; i += 384) {
        int k = i / PT, p = i - k*PT;
        out[((size_t)b*KP1 + k)*NP + p0 + p] = a_sm[p*PAD_K + k];
    }

    // v accumulation
    u64 vacc[8][2];
    #pragma unroll
    for (int kp = 0; kp < 8; kp++) { vacc[kp][0] = 0ULL; vacc[kp][1] = 0ULL; }

    const float* xb = x + ((size_t)b*NP + p0)*ND;
    #pragma unroll 4
    for (int p = 0; p < PT; p++) {
        float2 xv = __ldg((const float2*)(xb + (size_t)p*ND) + t);  // coalesced 3 KB
        u64 x0 = pack2(xv.x, xv.x), x1 = pack2(xv.y, xv.y);
        const ulonglong2* a2 = (const ulonglong2*)(a_sm + p*PAD_K); // 16B-aligned
        ulonglong2 A0 = a2[0], A1 = a2[1], A2 = a2[2], A3 = a2[3];
        u64 apr[8] = { A0.x, A0.y, A1.x, A1.y, A2.x, A2.y, A3.x, A3.y };
        #pragma unroll
        for (int kp = 0; kp < 8; kp++) {
            vacc[kp][0] = fma2(apr[kp], x0, vacc[kp][0]);
            vacc[kp][1] = fma2(apr[kp], x1, vacc[kp][1]);
        }
    }

    // epilogue: float2 atomics per k (vacc[kp][dd] = (v[2kp], v[2kp+1]) at d=2t+dd)
    float2* gv2 = (float2*)(g_v + (size_t)b*KF*ND);
    #pragma unroll
    for (int kp = 0; kp < 8; kp++) {
        float2 h0 = unpack2(vacc[kp][0]);   // (k=2kp, k=2kp+1) at d=2t
        float2 h1 = unpack2(vacc[kp][1]);   // (k=2kp, k=2kp+1) at d=2t+1
        atomicAdd(&gv2[(size_t)(2*kp    )*(ND/2) + t], make_float2(h0.x, h1.x));
        atomicAdd(&gv2[(size_t)(2*kp + 1)*(ND/2) + t], make_float2(h0.y, h1.y));
    }
}

// ---------------------------------------------------------------------------
// k2a: LayerNorm over D for each (b,k). Applies the /P scaling.
// Re-zeroes g_v (read-then-clear) and seeds parts/agg with the bias.
// ---------------------------------------------------------------------------
__global__ __launch_bounds__(256, 4)
void k2a(float* __restrict__ out,
         const float* __restrict__ gamma, const float* __restrict__ beta,
         const float* __restrict__ b_cls)
{
    const int bk = blockIdx.x;            // b*16 + k
    const int t = threadIdx.x;
    __shared__ float red[16];
    __shared__ float stats[2];
    float* gv = g_v + (size_t)bk*ND;
    const float invP = 1.f / (float)NP;

    float v[3]; float s = 0.f, sq = 0.f;
    #pragma unroll
    for (int i = 0; i < 3; i++) {
        float val = gv[t + i*256] * invP;
        gv[t + i*256] = 0.f;              // re-zero for next replay's k1b
        v[i] = val; s += val; sq += val*val;
    }

    // seed logits_parts / logits_agg with the classifier bias
    if (t < NC) {
        float bcv = b_cls[t];
        out[OFF_PARTS + (size_t)bk*NC + t] = bcv;
        if ((bk & 15) == 0) out[OFF_AGG + (size_t)(bk >> 4)*NC + t] = bcv;
    }

    #pragma unroll
    for (int o = 16; o; o >>= 1) {
        s  += __shfl_xor_sync(0xffffffffu, s, o);
        sq += __shfl_xor_sync(0xffffffffu, sq, o);
    }
    if ((t & 31) == 0) { red[t >> 5] = s; red[8 + (t >> 5)] = sq; }
    __syncthreads();
    if (t == 0) {
        float S = 0.f, Q = 0.f;
        #pragma unroll
        for (int w = 0; w < 8; w++) { S += red[w]; Q += red[8 + w]; }
        float mu  = S * (1.f/ND);
        float var = Q * (1.f/ND) - mu*mu;
        stats[0] = mu; stats[1] = rsqrtf(var + 1e-6f);
    }
    __syncthreads();
    const float mu = stats[0], rs = stats[1];
    #pragma unroll
    for (int i = 0; i < 3; i++) {
        int d = t + i*256;
        out[OFF_VN + (size_t)bk*ND + d] = (v[i] - mu) * rs * gamma[d] + beta[d];
    }
}

// ---------------------------------------------------------------------------
// k2b: logits_parts[b,k,c] += vn[b,k,dchunk] @ w[dchunk,c]; agg folded in.
// 16 d-chunks of 48 per image -> 512 blocks; w L2-resident.
// ---------------------------------------------------------------------------
#define DCH 48
__global__ __launch_bounds__(256, 4)
void k2b(const float* __restrict__ w, float* __restrict__ out)
{
    const int dc = blockIdx.x;            // 0..15
    const int b  = blockIdx.y;
    const int t  = threadIdx.x;
    __shared__ u64 vn_s[KF*(DCH/2)];      // packed d-pairs (3 KB)

    const float* vn = out + OFF_VN + (size_t)b*KF*ND + dc*DCH;
    for (int i = t; i < KF*(DCH/2); i += 256) {
        int k = i / (DCH/2), dp = i - k*(DCH/2);
        float2 v = *(const float2*)&vn[(size_t)k*ND + 2*dp];
        vn_s[i] = pack2(v.x, v.y);
    }
    __syncthreads();

    if (t < NC) {
        const float* wp = w + (size_t)(dc*DCH)*NC + t;   // coalesced in c
        u64 acc[KF];
        #pragma unroll
        for (int k = 0; k < KF; k++) acc[k] = 0ULL;
        #pragma unroll 8
        for (int dp = 0; dp < DCH/2; dp++) {
            float w0 = __ldg(wp + (size_t)(2*dp)*NC);
            float w1 = __ldg(wp + (size_t)(2*dp + 1)*NC);
            u64 wv = pack2(w0, w1);
            #pragma unroll
            for (int k = 0; k < KF; k++)
                acc[k] = fma2(vn_s[k*(DCH/2) + dp], wv, acc[k]);
        }
        float* parts = out + OFF_PARTS + (size_t)b*KF*NC + t;
        float ssum = 0.f;
        #pragma unroll
        for (int k = 0; k < KF; k++) {
            float2 h = unpack2(acc[k]);
            float s = h.x + h.y;
            atomicAdd(parts + (size_t)k*NC, s);
            ssum += s;
        }
        atomicAdd(out + OFF_AGG + b*NC + t, ssum * (1.f/KF));
    }
}

// ---------------------------------------------------------------------------
extern "C" void kernel_launch(void* const* d_in, const int* in_sizes, int n_in,
                              void* d_out, int out_size)
{
    const float* x     = (const float*)d_in[0];  // (32,24,24,768)
    const float* proto = (const float*)d_in[1];  // (17,768)
    const float* gamma = (const float*)d_in[2];  // (768,)
    const float* beta  = (const float*)d_in[3];  // (768,)
    const float* w     = (const float*)d_in[4];  // (768,200)
    const float* bc    = (const float*)d_in[5];  // (200,)
    float* out = (float*)d_out;

    const size_t smem_a = (size_t)(KP1*ND + 8*KP1*4 + KP1 + 3) * sizeof(float); // ~54.5 KB
    cudaFuncSetAttribute(k1a, cudaFuncAttributeMaxDynamicSharedMemorySize, (int)smem_a);

    k1a<<<NB*18, 256, smem_a>>>(x, proto);
    k1b<<<dim3(16, NB), 384>>>(x, out);
    k2a<<<NB*KF, 256>>>(out, gamma, beta, bc);
    k2b<<<dim3(16, NB), 256>>>(w, out);
}